// round 1
// baseline (speedup 1.0000x reference)
#include <cuda_runtime.h>
#include <math.h>
#include <stdint.h>

#define NB 2
#define NA 16384
#define NM 32
#define NC 15

#define PI_D 3.14159265358979323846

// ---------------- scratch (static device globals; no allocation) ----------------
__device__ float  g_ov[2][NB][NA][NM];     // phase(bf/af), img, anchor, gt
__device__ float  g_md[NB][NA][NM];
__device__ int    g_pairs[2 * NB * NA * NM];
__device__ int    g_pairCount;
__device__ float  g_ioumax[NB][NA];
__device__ int    g_iouarg[NB][NA];
__device__ int    g_pos[NB][NA];
__device__ float  g_mw[NB][NA];
__device__ float  g_maxgt[NB][NM];
__device__ int    g_arggt[NB][NM];
__device__ float  g_maxpos[NB][NM];
__device__ int    g_argpos[NB][NM];
__device__ double g_gtx[NB][NM][4];
__device__ double g_gty[NB][NM][4];
__device__ double g_gtsq[NB][NM][4];       // x1,y1,x2,y2 of min-area square
__device__ double g_gtsqarea[NB][NM];
__device__ double g_gtarea[NB][NM];        // w*h
__device__ double g_cls_sum[NB];
__device__ double g_reg_sum[NB];
__device__ int    g_numpos[NB];

// ---------------- geometry ----------------
// Sutherland-Hodgman: clip subject quad (ax,ay) by clipper quad (bx,by) (CCW), shoelace area.
__device__ double quad_inter_area(const double* ax, const double* ay,
                                  const double* bx, const double* by) {
    double px[10], py[10], qx[10], qy[10];
    int n = 4;
    for (int i = 0; i < 4; i++) { px[i] = ax[i]; py[i] = ay[i]; }
    for (int e = 0; e < 4; e++) {
        double x0 = bx[e], y0 = by[e];
        int e2 = (e + 1) & 3;
        double dx = bx[e2] - x0, dy = by[e2] - y0;
        int m = 0;
        double xprev = px[n - 1], yprev = py[n - 1];
        double dprev = dx * (yprev - y0) - dy * (xprev - x0);
        for (int i = 0; i < n; i++) {
            double xc = px[i], yc = py[i];
            double dc = dx * (yc - y0) - dy * (xc - x0);
            bool inc = (dc >= 0.0), inp = (dprev >= 0.0);
            if (inc != inp) {
                double t = dprev / (dprev - dc);
                if (m < 10) { qx[m] = xprev + t * (xc - xprev); qy[m] = yprev + t * (yc - yprev); m++; }
            }
            if (inc) { if (m < 10) { qx[m] = xc; qy[m] = yc; m++; } }
            dprev = dc; xprev = xc; yprev = yc;
        }
        n = m;
        if (n == 0) return 0.0;
        for (int i = 0; i < n; i++) { px[i] = qx[i]; py[i] = qy[i]; }
    }
    if (n < 3) return 0.0;
    double s = 0.0;
    double xp = px[n - 1], yp = py[n - 1];
    for (int i = 0; i < n; i++) { s += xp * py[i] - px[i] * yp; xp = px[i]; yp = py[i]; }
    return 0.5 * fabs(s);
}

__device__ __forceinline__ void rbox_corners_d(double cx, double cy, double w, double h,
                                               double ang_deg, double* X, double* Y) {
    double th = ang_deg * (PI_D / 180.0);
    double c = cos(th), s = sin(th);
    const double lx[4] = {-0.5, 0.5, 0.5, -0.5};
    const double ly[4] = {-0.5, -0.5, 0.5, 0.5};
#pragma unroll
    for (int k = 0; k < 4; k++) {
        double dx = w * lx[k], dy = h * ly[k];
        X[k] = cx + dx * c - dy * s;
        Y[k] = cy + dx * s + dy * c;
    }
}

// ---------------- kernels ----------------
__global__ void k_init(const float* __restrict__ ann) {
    int t = threadIdx.x;
    if (t == 0) g_pairCount = 0;
    if (t < NB) { g_cls_sum[t] = 0.0; g_reg_sum[t] = 0.0; g_numpos[t] = 0; }
    if (t < NB * NM) {
        int img = t / NM, j = t % NM;
        const float* g = ann + (size_t)(img * NM + j) * 6;
        double cx = g[0], cy = g[1], w = g[2], h = g[3], a = g[4];
        double X[4], Y[4];
        rbox_corners_d(cx, cy, w, h, a, X, Y);
#pragma unroll
        for (int k = 0; k < 4; k++) { g_gtx[img][j][k] = X[k]; g_gty[img][j][k] = Y[k]; }
        double s = 0.5 * fmax(w, h);
        double x1 = cx - s, y1 = cy - s, x2 = cx + s, y2 = cy + s;
        g_gtsq[img][j][0] = x1; g_gtsq[img][j][1] = y1;
        g_gtsq[img][j][2] = x2; g_gtsq[img][j][3] = y2;
        g_gtsqarea[img][j] = (x2 - x1) * (y2 - y1);
        g_gtarea[img][j] = w * h;
    }
}

__global__ void k_filter(const float* __restrict__ anc, const float* __restrict__ ranc) {
    int idx = blockIdx.x * blockDim.x + threadIdx.x;
    if (idx >= NB * NA * NM) return;
    int j = idx & (NM - 1);
    int a = (idx >> 5) & (NA - 1);
    int img = idx >> 19;
    double gx1 = g_gtsq[img][j][0], gy1 = g_gtsq[img][j][1];
    double gx2 = g_gtsq[img][j][2], gy2 = g_gtsq[img][j][3];
    double gar = g_gtsqarea[img][j];
#pragma unroll
    for (int ph = 0; ph < 2; ph++) {
        const float* p = (ph ? ranc : anc) + (size_t)(img * NA + a) * 5;
        double cx = p[0], cy = p[1], w = p[2], h = p[3];
        double s = 0.5 * fmax(w, h);
        double x1 = cx - s, y1 = cy - s, x2 = cx + s, y2 = cy + s;
        double aar = (x2 - x1) * (y2 - y1);
        double wx = fmin(x2, gx2) - fmax(x1, gx1); wx = fmax(wx, 0.0);
        double wy = fmin(y2, gy2) - fmax(y1, gy1); wy = fmax(wy, 0.0);
        double inter = wx * wy;
        double ind = inter / (aar + gar - inter + 1e-8);
        if (ind >= 0.1) {
            int k = atomicAdd(&g_pairCount, 1);
            g_pairs[k] = (img << 20) | (a << 6) | (j << 1) | ph;
        } else {
            g_ov[ph][img][a][j] = 0.0f;
        }
    }
}

__global__ void k_heavy(const float* __restrict__ anc, const float* __restrict__ ranc) {
    int total = g_pairCount;
    for (int idx = blockIdx.x * blockDim.x + threadIdx.x; idx < total;
         idx += gridDim.x * blockDim.x) {
        int code = g_pairs[idx];
        int ph = code & 1;
        int j = (code >> 1) & 31;
        int a = (code >> 6) & (NA - 1);
        int img = (code >> 20) & 1;
        const float* p = (ph ? ranc : anc) + (size_t)(img * NA + a) * 5;
        double cx = p[0], cy = p[1], w = p[2], h = p[3], angd = p[4];
        double AX[4], AY[4];
        rbox_corners_d(cx, cy, w, h, angd, AX, AY);
        double BX[4], BY[4];
#pragma unroll
        for (int k = 0; k < 4; k++) { BX[k] = g_gtx[img][j][k]; BY[k] = g_gty[img][j][k]; }
        double inter = quad_inter_area(AX, AY, BX, BY);
        double iou = inter / (w * h + g_gtarea[img][j] - inter + 1e-8);
        g_ov[ph][img][a][j] = (float)iou;
    }
}

__global__ void k_rowmax() {
    int w = blockIdx.x * 8 + (threadIdx.x >> 5);   // global warp id = anchor id
    int lane = threadIdx.x & 31;
    int a = w & (NA - 1);
    int img = w >> 14;
    float bf = g_ov[0][img][a][lane];
    float af = g_ov[1][img][a][lane];
    float md = fabsf(bf + 0.5f * af - fabsf(af - bf));
    g_md[img][a][lane] = md;
    float bv = md; int bi = lane;
#pragma unroll
    for (int off = 16; off > 0; off >>= 1) {
        float ov = __shfl_xor_sync(0xffffffffu, bv, off);
        int   oi = __shfl_xor_sync(0xffffffffu, bi, off);
        if (ov > bv || (ov == bv && oi < bi)) { bv = ov; bi = oi; }
    }
    if (lane == 0) { g_ioumax[img][a] = bv; g_iouarg[img][a] = bi; }
}

template <bool GATE>
__global__ void k_colmax_t() {
    int img = blockIdx.x >> 5;
    int j = blockIdx.x & 31;
    int tid = threadIdx.x;
    __shared__ float sv[256];
    __shared__ int si[256];
    float best = -INFINITY; int bidx = 0;
    for (int a = tid; a < NA; a += 256) {
        float v;
        if (GATE) v = g_pos[img][a] ? g_md[img][a][j] : -INFINITY;
        else      v = g_md[img][a][j];
        if (v > best) { best = v; bidx = a; }
    }
    sv[tid] = best; si[tid] = bidx;
    __syncthreads();
    for (int st = 128; st > 0; st >>= 1) {
        if (tid < st) {
            if (sv[tid + st] > sv[tid] || (sv[tid + st] == sv[tid] && si[tid + st] < si[tid])) {
                sv[tid] = sv[tid + st]; si[tid] = si[tid + st];
            }
        }
        __syncthreads();
    }
    if (tid == 0) {
        if (GATE) { g_maxpos[img][j] = sv[0]; g_argpos[img][j] = si[0]; }
        else      { g_maxgt[img][j] = sv[0];  g_arggt[img][j] = si[0]; }
    }
}

__global__ void k_pos() {
    int idx = blockIdx.x * blockDim.x + threadIdx.x;
    if (idx >= NB * NA) return;
    int img = idx >> 14, a = idx & (NA - 1);
    g_pos[img][a] = (g_ioumax[img][a] >= 0.5f) ? 1 : 0;
}

__global__ void k_force() {
    int t = threadIdx.x;
    if (t < NB * NM) {
        int img = t >> 5, j = t & 31;
        if (g_maxgt[img][j] < 0.5f) g_pos[img][g_arggt[img][j]] = 1;
    }
}

__global__ void k_mw() {
    int w = blockIdx.x * 8 + (threadIdx.x >> 5);
    int lane = threadIdx.x & 31;
    int a = w & (NA - 1);
    int img = w >> 14;
    int posa = g_pos[img][a];
    float md = g_md[img][a][lane];
    bool pm = ((md >= 0.5f) && posa) || (g_argpos[img][lane] == a);
    float comp = pm ? (1.0f - g_maxpos[img][lane]) : md;
    float v = comp + md;
#pragma unroll
    for (int off = 16; off > 0; off >>= 1) {
        float ov = __shfl_xor_sync(0xffffffffu, v, off);
        v = fmaxf(v, ov);
    }
    if (lane == 0) g_mw[img][a] = v;
}

__global__ void k_loss(const float* __restrict__ cls, const float* __restrict__ reg,
                       const float* __restrict__ anc, const float* __restrict__ ann) {
    int idx = blockIdx.x * blockDim.x + threadIdx.x;
    int img = idx >> 14, a = idx & (NA - 1);
    int tid = threadIdx.x;

    double csum = 0.0, rsum = 0.0;
    int posa = g_pos[img][a];
    float iomax = g_ioumax[img][a];
    int jm = g_iouarg[img][a];
    float mw = g_mw[img][a];
    const float* gt = ann + (size_t)(img * NM + jm) * 6;
    int lab = (int)gt[5];
    const float* crow = cls + (size_t)(img * NA + a) * NC;

    if (posa) {
#pragma unroll
        for (int c = 0; c < NC; c++) {
            float xr = crow[c];
            double x = fmin(fmax((double)xr, 0.0001), 1.0 - 0.0001);
            if (c == lab) {
                double fw = 0.25 * (1.0 - x) * (1.0 - x);
                double bce = -log(x + 1e-6);
                csum += fw * bce * ((double)mw + 1.0);
            } else {
                double fw = 0.75 * x * x;
                double bce = -log(1.0 - x + 1e-6);
                csum += fw * bce;
            }
        }
        // regression
        const float* ap = anc + (size_t)(img * NA + a) * 5;
        const float* rg = reg + (size_t)(img * NA + a) * 5;
        double aw = ap[2], ah = ap[3];
        double gw = fmax((double)gt[2], 1.0), gh = fmax((double)gt[3], 1.0);
        double tv[5];
        tv[0] = ((double)gt[0] - (double)ap[0]) / aw;
        tv[1] = ((double)gt[1] - (double)ap[1]) / ah;
        tv[2] = log(gw / aw);
        tv[3] = log(gh / ah);
        tv[4] = tan((double)gt[4] * (PI_D / 180.0)) - tan((double)ap[4] * (PI_D / 180.0));
        const double BETA = 1.0 / 9.0;
#pragma unroll
        for (int k = 0; k < 5; k++) {
            double diff = fabs((double)rg[k] - tv[k]);
            double sl = (diff < BETA) ? (0.5 * diff * diff / BETA) : (diff - 0.5 * BETA);
            rsum += sl * (double)mw;
        }
    } else if (iomax < 0.4f) {
        // tgt = 0 for all classes
#pragma unroll
        for (int c = 0; c < NC; c++) {
            float xr = crow[c];
            double x = fmin(fmax((double)xr, 0.0001), 1.0 - 0.0001);
            double fw = 0.75 * x * x;
            double bce = -log(1.0 - x + 1e-6);
            csum += fw * bce;
        }
    } // else tgt = -1 everywhere: contributes 0

    __shared__ double s_c[256];
    __shared__ double s_r[256];
    __shared__ int s_n[256];
    s_c[tid] = csum; s_r[tid] = rsum; s_n[tid] = posa;
    __syncthreads();
    for (int st = 128; st > 0; st >>= 1) {
        if (tid < st) {
            s_c[tid] += s_c[tid + st];
            s_r[tid] += s_r[tid + st];
            s_n[tid] += s_n[tid + st];
        }
        __syncthreads();
    }
    if (tid == 0) {
        atomicAdd(&g_cls_sum[img], s_c[0]);
        atomicAdd(&g_reg_sum[img], s_r[0]);
        atomicAdd(&g_numpos[img], s_n[0]);
    }
}

__global__ void k_final(float* __restrict__ out) {
    double lc = 0.0, lr = 0.0;
#pragma unroll
    for (int img = 0; img < NB; img++) {
        int np = g_numpos[img];
        lc += g_cls_sum[img] / fmax((double)np, 1.0);
        if (np > 0) {
            int d = np * 5; if (d < 1) d = 1;
            lr += g_reg_sum[img] / (double)d;
        }
    }
    out[0] = (float)(lc / (double)NB);
    out[1] = (float)(lr / (double)NB);
}

// ---------------- launcher ----------------
extern "C" void kernel_launch(void* const* d_in, const int* in_sizes, int n_in,
                              void* d_out, int out_size) {
    const float* cls  = (const float*)d_in[0];
    const float* reg  = (const float*)d_in[1];
    const float* anc  = (const float*)d_in[2];
    const float* ranc = (const float*)d_in[3];
    const float* ann  = (const float*)d_in[4];
    float* out = (float*)d_out;

    k_init<<<1, 64>>>(ann);
    k_filter<<<(NB * NA * NM) / 256, 256>>>(anc, ranc);
    k_heavy<<<1024, 256>>>(anc, ranc);
    k_rowmax<<<(NB * NA) / 8, 256>>>();
    k_colmax_t<false><<<NB * NM, 256>>>();
    k_pos<<<(NB * NA) / 256, 256>>>();
    k_force<<<1, 64>>>();
    k_colmax_t<true><<<NB * NM, 256>>>();
    k_mw<<<(NB * NA) / 8, 256>>>();
    k_loss<<<(NB * NA) / 256, 256>>>(cls, reg, anc, ann);
    k_final<<<1, 1>>>(out);
}

// round 2
// speedup vs baseline: 5.1055x; 5.1055x over previous
#include <cuda_runtime.h>
#include <math.h>
#include <stdint.h>

#define NB 2
#define NA 16384
#define NM 32
#define NC 15
#define PI_F 3.14159265358979323846f

typedef unsigned long long ull;

// ---------------- scratch ----------------
__device__ float g_ov[2][NB][NA][NM];
__device__ float g_md[NB][NA][NM];
__device__ int   g_pairs[2 * NB * NA * NM];
__device__ int   g_pairCount;
__device__ float g_ioumax[NB][NA];
__device__ int   g_iouarg[NB][NA];
__device__ int   g_pos[NB][NA];
__device__ float g_maxpos[NB][NM];
__device__ int   g_argpos[NB][NM];
__device__ ull   g_colkeyF[NB][NM];
__device__ float g_gtx[NB][NM][4];
__device__ float g_gty[NB][NM][4];
__device__ float g_gtsq[NB][NM][4];
__device__ float g_gtsqarea[NB][NM];
__device__ float g_gtarea[NB][NM];
__device__ double g_cls_sum[NB];
__device__ double g_reg_sum[NB];
__device__ int    g_numpos[NB];

// key: value-major, smaller index wins ties (matches jnp.argmax first-occurrence).
// md >= 0 always, so float bits are monotonic.
__device__ __forceinline__ ull packkey(float v, unsigned idx) {
    return ((ull)__float_as_uint(v) << 32) | (ull)(0xFFFFFFFFu - idx);
}
__device__ __forceinline__ float keyval(ull k) { return __uint_as_float((unsigned)(k >> 32)); }
__device__ __forceinline__ unsigned keyidx(ull k) { return 0xFFFFFFFFu - (unsigned)(k & 0xFFFFFFFFu); }

__device__ __forceinline__ ull warp_max_ull(ull v) {
#pragma unroll
    for (int off = 16; off > 0; off >>= 1) {
        ull o = __shfl_xor_sync(0xffffffffu, v, off);
        if (o > v) v = o;
    }
    return v;
}
__device__ __forceinline__ float warp_sum_f(float v) {
#pragma unroll
    for (int off = 16; off > 0; off >>= 1) v += __shfl_xor_sync(0xffffffffu, v, off);
    return v;
}
__device__ __forceinline__ float warp_max_f(float v) {
#pragma unroll
    for (int off = 16; off > 0; off >>= 1) v = fmaxf(v, __shfl_xor_sync(0xffffffffu, v, off));
    return v;
}

// Sutherland-Hodgman in f32 on CENTERED coordinates.
__device__ float quad_inter_area_f(const float* ax, const float* ay,
                                   const float* bx, const float* by) {
    float px[10], py[10], qx[10], qy[10];
    int n = 4;
#pragma unroll
    for (int i = 0; i < 4; i++) { px[i] = ax[i]; py[i] = ay[i]; }
    for (int e = 0; e < 4; e++) {
        float x0 = bx[e], y0 = by[e];
        int e2 = (e + 1) & 3;
        float dx = bx[e2] - x0, dy = by[e2] - y0;
        int m = 0;
        float xprev = px[n - 1], yprev = py[n - 1];
        float dprev = dx * (yprev - y0) - dy * (xprev - x0);
        for (int i = 0; i < n; i++) {
            float xc = px[i], yc = py[i];
            float dc = dx * (yc - y0) - dy * (xc - x0);
            bool inc = (dc >= 0.0f), inp = (dprev >= 0.0f);
            if (inc != inp) {
                float t = dprev / (dprev - dc);
                if (m < 10) { qx[m] = xprev + t * (xc - xprev); qy[m] = yprev + t * (yc - yprev); m++; }
            }
            if (inc) { if (m < 10) { qx[m] = xc; qy[m] = yc; m++; } }
            dprev = dc; xprev = xc; yprev = yc;
        }
        n = m;
        if (n == 0) return 0.0f;
        for (int i = 0; i < n; i++) { px[i] = qx[i]; py[i] = qy[i]; }
    }
    if (n < 3) return 0.0f;
    float s = 0.0f;
    float xp = px[n - 1], yp = py[n - 1];
    for (int i = 0; i < n; i++) { s += xp * py[i] - px[i] * yp; xp = px[i]; yp = py[i]; }
    return 0.5f * fabsf(s);
}

__device__ __forceinline__ void corners_f(float cx, float cy, float w, float h,
                                          float ang_deg, float* X, float* Y) {
    float th = ang_deg * (PI_F / 180.0f);
    float s, c;
    sincosf(th, &s, &c);
    const float lx[4] = {-0.5f, 0.5f, 0.5f, -0.5f};
    const float ly[4] = {-0.5f, -0.5f, 0.5f, 0.5f};
#pragma unroll
    for (int k = 0; k < 4; k++) {
        float dx = w * lx[k], dy = h * ly[k];
        X[k] = cx + dx * c - dy * s;
        Y[k] = cy + dx * s + dy * c;
    }
}

// ---------------- kernels ----------------
__global__ void k_init(const float* __restrict__ ann) {
    int t = threadIdx.x;
    if (t < NB) { g_cls_sum[t] = 0.0; g_reg_sum[t] = 0.0; g_numpos[t] = 0; }
    if (t == 2) g_pairCount = 0;
    if (t < NB * NM) {
        int img = t >> 5, j = t & 31;
        g_colkeyF[img][j] = 0ull;
        const float* g = ann + (size_t)(img * NM + j) * 6;
        float cx = g[0], cy = g[1], w = g[2], h = g[3], a = g[4];
        float X[4], Y[4];
        corners_f(cx, cy, w, h, a, X, Y);
#pragma unroll
        for (int k = 0; k < 4; k++) { g_gtx[img][j][k] = X[k]; g_gty[img][j][k] = Y[k]; }
        float s = fmaxf(w, h) * 0.5f;
        float x1 = cx - s, y1 = cy - s, x2 = cx + s, y2 = cy + s;
        g_gtsq[img][j][0] = x1; g_gtsq[img][j][1] = y1;
        g_gtsq[img][j][2] = x2; g_gtsq[img][j][3] = y2;
        g_gtsqarea[img][j] = (x2 - x1) * (y2 - y1);
        g_gtarea[img][j] = w * h;
    }
}

// one thread per (img, anchor, phase); loops over 32 gts
__global__ void k_filter(const float* __restrict__ anc, const float* __restrict__ ranc) {
    int idx = blockIdx.x * blockDim.x + threadIdx.x;   // [0, NB*NA*2)
    int lane = threadIdx.x & 31;
    int ph = idx & 1;
    int a = (idx >> 1) & (NA - 1);
    int img = idx >> 15;

    const float* p = (ph ? ranc : anc) + (size_t)(img * NA + a) * 5;
    float cx = p[0], cy = p[1], w = p[2], h = p[3];
    float s = fmaxf(w, h) * 0.5f;
    float x1 = cx - s, y1 = cy - s, x2 = cx + s, y2 = cy + s;
    float aar = (x2 - x1) * (y2 - y1);

    int m = 0;
    int codes[NM];
#pragma unroll 4
    for (int j = 0; j < NM; j++) {
        float gx1 = g_gtsq[img][j][0], gy1 = g_gtsq[img][j][1];
        float gx2 = g_gtsq[img][j][2], gy2 = g_gtsq[img][j][3];
        float wx = fminf(x2, gx2) - fmaxf(x1, gx1); wx = fmaxf(wx, 0.0f);
        float wy = fminf(y2, gy2) - fmaxf(y1, gy1); wy = fmaxf(wy, 0.0f);
        float inter = wx * wy;
        float ind = inter / (aar + g_gtsqarea[img][j] - inter + 1e-8f);
        if (ind >= 0.1f) {
            codes[m++] = (img << 20) | (a << 6) | (j << 1) | ph;
        } else {
            g_ov[ph][img][a][j] = 0.0f;
        }
    }
    // warp-aggregated append
    int incl = m;
#pragma unroll
    for (int off = 1; off < 32; off <<= 1) {
        int n = __shfl_up_sync(0xffffffffu, incl, off);
        if (lane >= off) incl += n;
    }
    int total = __shfl_sync(0xffffffffu, incl, 31);
    int base = 0;
    if (lane == 0 && total > 0) base = atomicAdd(&g_pairCount, total);
    base = __shfl_sync(0xffffffffu, base, 0);
    int off0 = base + incl - m;
    for (int i = 0; i < m; i++) g_pairs[off0 + i] = codes[i];
}

__global__ void k_heavy(const float* __restrict__ anc, const float* __restrict__ ranc) {
    int total = g_pairCount;
    for (int idx = blockIdx.x * blockDim.x + threadIdx.x; idx < total;
         idx += gridDim.x * blockDim.x) {
        int code = g_pairs[idx];
        int ph = code & 1;
        int j = (code >> 1) & 31;
        int a = (code >> 6) & (NA - 1);
        int img = (code >> 20) & 1;
        const float* p = (ph ? ranc : anc) + (size_t)(img * NA + a) * 5;
        float cx = p[0], cy = p[1], w = p[2], h = p[3], ang = p[4];
        // anchor corners centered at (cx,cy)
        float th = ang * (PI_F / 180.0f);
        float sn, cs;
        sincosf(th, &sn, &cs);
        const float lx[4] = {-0.5f, 0.5f, 0.5f, -0.5f};
        const float ly[4] = {-0.5f, -0.5f, 0.5f, 0.5f};
        float AX[4], AY[4], BX[4], BY[4];
#pragma unroll
        for (int k = 0; k < 4; k++) {
            float dx = w * lx[k], dy = h * ly[k];
            AX[k] = dx * cs - dy * sn;
            AY[k] = dx * sn + dy * cs;
            BX[k] = g_gtx[img][j][k] - cx;
            BY[k] = g_gty[img][j][k] - cy;
        }
        float inter = quad_inter_area_f(AX, AY, BX, BY);
        float iou = inter / (w * h + g_gtarea[img][j] - inter + 1e-8f);
        g_ov[ph][img][a][j] = iou;
    }
}

// 64 blocks x 1024 threads. Each warp handles 16 anchors (lane = gt column).
// Produces: g_md, g_ioumax/g_iouarg/g_pos (per anchor), g_colkeyF (per column).
__global__ void k_rowmax() {
    int warp = threadIdx.x >> 5, lane = threadIdx.x & 31;
    int img = blockIdx.x >> 5;
    int abase = (blockIdx.x & 31) * 512 + warp * 16;
    ull ckey = 0ull;
#pragma unroll
    for (int k = 0; k < 16; k++) {
        int a = abase + k;
        float bf = g_ov[0][img][a][lane];
        float af = g_ov[1][img][a][lane];
        float md = fabsf(bf + 0.5f * af - fabsf(af - bf));
        g_md[img][a][lane] = md;
        ull rk = warp_max_ull(packkey(md, (unsigned)lane));
        if (lane == 0) {
            float bv = keyval(rk);
            g_ioumax[img][a] = bv;
            g_iouarg[img][a] = (int)keyidx(rk);
            g_pos[img][a] = (bv >= 0.5f) ? 1 : 0;
        }
        ull ck = packkey(md, (unsigned)a);
        if (ck > ckey) ckey = ck;
    }
    __shared__ ull s[32][33];
    s[warp][lane] = ckey;
    __syncthreads();
    // warp w reduces column w
    ull v = s[lane][warp];
    v = warp_max_ull(v);
    if (lane == 0) atomicMax(&g_colkeyF[img][warp], v);
}

// 2 blocks (one per img) x 1024. Applies "force", then computes pos-gated colmax.
__global__ void k_force_colmaxT() {
    int img = blockIdx.x;
    int tid = threadIdx.x;
    int warp = tid >> 5, lane = tid & 31;
    if (tid < NM) {
        ull k = g_colkeyF[img][tid];
        if (keyval(k) < 0.5f) g_pos[img][(int)keyidx(k)] = 1;
    }
    __syncthreads();
    // each warp scans 512 anchors; lane tracks column=lane
    ull local = 0ull;
    int base = warp * 512;
    for (int c = 0; c < 512; c += 32) {
        int a0 = base + c;
        int p = g_pos[img][a0 + lane];
        unsigned mask = __ballot_sync(0xffffffffu, p != 0);
        while (mask) {
            int b = __ffs(mask) - 1;
            mask &= mask - 1;
            int a = a0 + b;
            float md = g_md[img][a][lane];
            ull k = packkey(md, (unsigned)a);
            if (k > local) local = k;
        }
    }
    __shared__ ull s[32][33];
    s[warp][lane] = local;
    __syncthreads();
    ull v = s[lane][warp];
    v = warp_max_ull(v);
    if (lane == 0) {
        g_maxpos[img][warp] = keyval(v);
        g_argpos[img][warp] = (int)keyidx(v);
    }
}

// warp per anchor: computes mw inline, focal cls loss, smooth-L1 reg loss.
__global__ void k_loss(const float* __restrict__ cls, const float* __restrict__ reg,
                       const float* __restrict__ anc, const float* __restrict__ ann) {
    int gw = blockIdx.x * 8 + (threadIdx.x >> 5);
    int lane = threadIdx.x & 31;
    int warp = threadIdx.x >> 5;
    int a = gw & (NA - 1);
    int img = gw >> 14;

    float md = g_md[img][a][lane];
    int posa; float iomax; int jm;
    if (lane == 0) {
        posa = g_pos[img][a];
        iomax = g_ioumax[img][a];
        jm = g_iouarg[img][a];
    }
    posa = __shfl_sync(0xffffffffu, posa, 0);
    iomax = __shfl_sync(0xffffffffu, iomax, 0);
    jm = __shfl_sync(0xffffffffu, jm, 0);

    float maxpos = g_maxpos[img][lane];
    int argpos = g_argpos[img][lane];
    bool pm = ((md >= 0.5f) && posa) || (argpos == a);
    float comp = pm ? (1.0f - maxpos) : md;
    float mw = warp_max_f(comp + md);

    float csum = 0.0f, rsum = 0.0f;
    if (posa) {
        const float* gt = ann + (size_t)(img * NM + jm) * 6;
        int lab = (int)gt[5];
        if (lane < NC) {
            float x = fminf(fmaxf(cls[(size_t)(img * NA + a) * NC + lane], 0.0001f),
                            1.0f - 0.0001f);
            if (lane == lab) {
                float fw = 0.25f * (1.0f - x) * (1.0f - x);
                csum = fw * (-logf(x + 1e-6f)) * (mw + 1.0f);
            } else {
                float fw = 0.75f * x * x;
                csum = fw * (-logf(1.0f - x + 1e-6f));
            }
        }
        if (lane < 5) {
            const float* ap = anc + (size_t)(img * NA + a) * 5;
            const float* rg = reg + (size_t)(img * NA + a) * 5;
            float tv;
            if (lane == 0) tv = (gt[0] - ap[0]) / ap[2];
            else if (lane == 1) tv = (gt[1] - ap[1]) / ap[3];
            else if (lane == 2) tv = logf(fmaxf(gt[2], 1.0f) / ap[2]);
            else if (lane == 3) tv = logf(fmaxf(gt[3], 1.0f) / ap[3]);
            else tv = tanf(gt[4] * (PI_F / 180.0f)) - tanf(ap[4] * (PI_F / 180.0f));
            float diff = fabsf(rg[lane] - tv);
            const float BETA = (float)(1.0 / 9.0);
            float sl = (diff < BETA) ? (0.5f * diff * diff / BETA) : (diff - 0.5f * BETA);
            rsum = sl * mw;
        }
    } else if (iomax < 0.4f) {
        if (lane < NC) {
            float x = fminf(fmaxf(cls[(size_t)(img * NA + a) * NC + lane], 0.0001f),
                            1.0f - 0.0001f);
            float fw = 0.75f * x * x;
            csum = fw * (-logf(1.0f - x + 1e-6f));
        }
    }
    float wc = warp_sum_f(csum);
    float wr = warp_sum_f(rsum);

    __shared__ double s_c[2][8];
    __shared__ double s_r[8];
    __shared__ int s_n[2][8];
    // note: all warps in a block share the same img (8 warps = 8 consecutive anchors)
    if (lane == 0) { s_c[0][warp] = (double)wc; s_r[warp] = (double)wr; s_n[0][warp] = posa; }
    __syncthreads();
    if (threadIdx.x == 0) {
        double tc = 0.0, tr = 0.0; int tn = 0;
#pragma unroll
        for (int i = 0; i < 8; i++) { tc += s_c[0][i]; tr += s_r[i]; tn += s_n[0][i]; }
        atomicAdd(&g_cls_sum[img], tc);
        atomicAdd(&g_reg_sum[img], tr);
        atomicAdd(&g_numpos[img], tn);
    }
}

__global__ void k_final(float* __restrict__ out) {
    double lc = 0.0, lr = 0.0;
#pragma unroll
    for (int img = 0; img < NB; img++) {
        int np = g_numpos[img];
        lc += g_cls_sum[img] / fmax((double)np, 1.0);
        if (np > 0) {
            long long d = (long long)np * 5;
            if (d < 1) d = 1;
            lr += g_reg_sum[img] / (double)d;
        }
    }
    out[0] = (float)(lc / (double)NB);
    out[1] = (float)(lr / (double)NB);
}

// ---------------- launcher ----------------
extern "C" void kernel_launch(void* const* d_in, const int* in_sizes, int n_in,
                              void* d_out, int out_size) {
    const float* cls  = (const float*)d_in[0];
    const float* reg  = (const float*)d_in[1];
    const float* anc  = (const float*)d_in[2];
    const float* ranc = (const float*)d_in[3];
    const float* ann  = (const float*)d_in[4];
    float* out = (float*)d_out;

    k_init<<<1, 128>>>(ann);
    k_filter<<<(NB * NA * 2) / 256, 256>>>(anc, ranc);
    k_heavy<<<256, 256>>>(anc, ranc);
    k_rowmax<<<64, 1024>>>();
    k_force_colmaxT<<<2, 1024>>>();
    k_loss<<<(NB * NA) / 8, 256>>>(cls, reg, anc, ann);
    k_final<<<1, 1>>>(out);
}

// round 3
// speedup vs baseline: 6.4768x; 1.2686x over previous
#include <cuda_runtime.h>
#include <math.h>
#include <stdint.h>

#define NB 2
#define NA 16384
#define NM 32
#define NC 15
#define PI_F 3.14159265358979323846f

typedef long long ll;

#define NEGK (-9223372036854775807ll - 1ll)
#define N4 NEGK, NEGK, NEGK, NEGK
#define N32 N4, N4, N4, N4, N4, N4, N4, N4

// ---------------- scratch (zero-init unless stated; state restored after each run) ----
__device__ float  g_md[NB][NA][NM];          // nonzero only at pair entries (rewritten each run)
__device__ ll     g_rowkey[NB][NA];          // identity = 0 ; reset by k_loss
__device__ ll     g_colkeyF[NB][NM];         // identity = 0 ; reset by k_final
__device__ ll     g_colkeyP[NB][NM] = {{N32}, {N32}};  // identity = NEGK ; reset by k_final
__device__ int    g_pairs[NB * NA * NM];
__device__ int    g_pairCount;               // reset by k_final
__device__ double g_cls_sum[NB];             // reset by k_final
__device__ double g_reg_sum[NB];
__device__ int    g_numpos[NB];

// key = (float_bits(v) << 32) - idx  (v >= 0). Max => larger v, then smaller idx.
// packkey(0,0) == 0, so zero is the natural identity.
__device__ __forceinline__ ll spack(float v, unsigned idx) {
    return (ll)((unsigned long long)__float_as_uint(v) << 32) - (ll)idx;
}
__device__ __forceinline__ void sdec(ll k, float& v, unsigned& idx) {
    unsigned lo = (unsigned)(k & 0xFFFFFFFFll);
    idx = (unsigned)(-(int)lo);
    unsigned vb = (unsigned)(((unsigned long long)(k + (ll)idx)) >> 32);
    v = __uint_as_float(vb);
}

__device__ __forceinline__ float warp_sum_f(float v) {
#pragma unroll
    for (int off = 16; off > 0; off >>= 1) v += __shfl_xor_sync(0xffffffffu, v, off);
    return v;
}

// Sutherland-Hodgman on centered f32 coordinates.
__device__ float quad_inter_area_f(const float* ax, const float* ay,
                                   const float* bx, const float* by) {
    float px[10], py[10], qx[10], qy[10];
    int n = 4;
#pragma unroll
    for (int i = 0; i < 4; i++) { px[i] = ax[i]; py[i] = ay[i]; }
    for (int e = 0; e < 4; e++) {
        float x0 = bx[e], y0 = by[e];
        int e2 = (e + 1) & 3;
        float dx = bx[e2] - x0, dy = by[e2] - y0;
        int m = 0;
        float xprev = px[n - 1], yprev = py[n - 1];
        float dprev = dx * (yprev - y0) - dy * (xprev - x0);
        for (int i = 0; i < n; i++) {
            float xc = px[i], yc = py[i];
            float dc = dx * (yc - y0) - dy * (xc - x0);
            bool inc = (dc >= 0.0f), inp = (dprev >= 0.0f);
            if (inc != inp) {
                float t = dprev / (dprev - dc);
                if (m < 10) { qx[m] = xprev + t * (xc - xprev); qy[m] = yprev + t * (yc - yprev); m++; }
            }
            if (inc) { if (m < 10) { qx[m] = xc; qy[m] = yc; m++; } }
            dprev = dc; xprev = xc; yprev = yc;
        }
        n = m;
        if (n == 0) return 0.0f;
        for (int i = 0; i < n; i++) { px[i] = qx[i]; py[i] = qy[i]; }
    }
    if (n < 3) return 0.0f;
    float s = 0.0f;
    float xp = px[n - 1], yp = py[n - 1];
    for (int i = 0; i < n; i++) { s += xp * py[i] - px[i] * yp; xp = px[i]; yp = py[i]; }
    return 0.5f * fabsf(s);
}

// ---------------- 1: filter (emit combined pairs with 2 phase flags) ----------------
__global__ void k_filter(const float* __restrict__ anc, const float* __restrict__ ranc,
                         const float* __restrict__ ann) {
    int idx = blockIdx.x * 256 + threadIdx.x;  // [0, NB*NA)
    int lane = threadIdx.x & 31;
    int a = idx & (NA - 1);
    int img = idx >> 14;

    __shared__ float sx1[NM], sy1[NM], sx2[NM], sy2[NM], sar[NM];
    if (threadIdx.x < NM) {
        const float* g = ann + (size_t)(img * NM + threadIdx.x) * 6;
        float cx = g[0], cy = g[1], w = g[2], h = g[3];
        float s = fmaxf(w, h) * 0.5f;
        float x1 = cx - s, y1 = cy - s, x2 = cx + s, y2 = cy + s;
        sx1[threadIdx.x] = x1; sy1[threadIdx.x] = y1;
        sx2[threadIdx.x] = x2; sy2[threadIdx.x] = y2;
        sar[threadIdx.x] = (x2 - x1) * (y2 - y1);
    }
    __syncthreads();

    const float* p = anc + (size_t)(img * NA + a) * 5;
    const float* q = ranc + (size_t)(img * NA + a) * 5;
    float s0 = fmaxf(p[2], p[3]) * 0.5f;
    float ax1 = p[0] - s0, ay1 = p[1] - s0, ax2 = p[0] + s0, ay2 = p[1] + s0;
    float aar = (ax2 - ax1) * (ay2 - ay1);
    float s1 = fmaxf(q[2], q[3]) * 0.5f;
    float rx1 = q[0] - s1, ry1 = q[1] - s1, rx2 = q[0] + s1, ry2 = q[1] + s1;
    float rar = (rx2 - rx1) * (ry2 - ry1);

    for (int j = 0; j < NM; j++) {
        float gx1 = sx1[j], gy1 = sy1[j], gx2 = sx2[j], gy2 = sy2[j], gar = sar[j];
        float wx = fmaxf(fminf(ax2, gx2) - fmaxf(ax1, gx1), 0.0f);
        float wy = fmaxf(fminf(ay2, gy2) - fmaxf(ay1, gy1), 0.0f);
        float i0 = wx * wy;
        bool f0 = (i0 / (aar + gar - i0 + 1e-8f)) >= 0.1f;
        wx = fmaxf(fminf(rx2, gx2) - fmaxf(rx1, gx1), 0.0f);
        wy = fmaxf(fminf(ry2, gy2) - fmaxf(ry1, gy1), 0.0f);
        float i1 = wx * wy;
        bool f1 = (i1 / (rar + gar - i1 + 1e-8f)) >= 0.1f;
        bool emit = f0 | f1;
        unsigned mask = __ballot_sync(0xffffffffu, emit);
        if (mask) {
            int leader = __ffs(mask) - 1;
            int rank = __popc(mask & ((1u << lane) - 1));
            int base = 0;
            if (lane == leader) base = atomicAdd(&g_pairCount, __popc(mask));
            base = __shfl_sync(0xffffffffu, base, leader);
            if (emit)
                g_pairs[base + rank] =
                    (img << 21) | (a << 7) | (j << 2) | ((int)f1 << 1) | (int)f0;
        }
    }
}

// ---------------- 2: heavy (clip + md + key atomics) ----------------
__global__ void k_heavy(const float* __restrict__ anc, const float* __restrict__ ranc,
                        const float* __restrict__ ann) {
    __shared__ float sgx[NB * NM][4], sgy[NB * NM][4];
    __shared__ float sgar[NB * NM];
    __shared__ ll scol[NB * NM];
    int t = threadIdx.x;
    if (t < NB * NM) {
        int img = t >> 5, j = t & 31;
        const float* g = ann + (size_t)(img * NM + j) * 6;
        float cx = g[0], cy = g[1], w = g[2], h = g[3];
        float th = g[4] * (PI_F / 180.0f);
        float sn, cs;
        sincosf(th, &sn, &cs);
        const float lx[4] = {-0.5f, 0.5f, 0.5f, -0.5f};
        const float ly[4] = {-0.5f, -0.5f, 0.5f, 0.5f};
#pragma unroll
        for (int k = 0; k < 4; k++) {
            float dx = w * lx[k], dy = h * ly[k];
            sgx[t][k] = cx + dx * cs - dy * sn;
            sgy[t][k] = cy + dx * sn + dy * cs;
        }
        sgar[t] = w * h;
        scol[t] = 0;
    }
    __syncthreads();

    int total = g_pairCount;
    const float lx[4] = {-0.5f, 0.5f, 0.5f, -0.5f};
    const float ly[4] = {-0.5f, -0.5f, 0.5f, 0.5f};
    for (int idx = blockIdx.x * blockDim.x + threadIdx.x; idx < total;
         idx += gridDim.x * blockDim.x) {
        int code = g_pairs[idx];
        int f0 = code & 1, f1 = (code >> 1) & 1;
        int j = (code >> 2) & 31;
        int a = (code >> 7) & (NA - 1);
        int img = (code >> 21) & 1;
        int gj = img * 32 + j;
        float gar = sgar[gj];
        float bf = 0.0f, af = 0.0f;
#pragma unroll
        for (int ph = 0; ph < 2; ph++) {
            if (!(ph ? f1 : f0)) continue;
            const float* p = (ph ? ranc : anc) + (size_t)(img * NA + a) * 5;
            float cx = p[0], cy = p[1], w = p[2], h = p[3];
            float th = p[4] * (PI_F / 180.0f);
            float sn, cs;
            sincosf(th, &sn, &cs);
            float AX[4], AY[4], BX[4], BY[4];
#pragma unroll
            for (int k = 0; k < 4; k++) {
                float dx = w * lx[k], dy = h * ly[k];
                AX[k] = dx * cs - dy * sn;
                AY[k] = dx * sn + dy * cs;
                BX[k] = sgx[gj][k] - cx;
                BY[k] = sgy[gj][k] - cy;
            }
            float inter = quad_inter_area_f(AX, AY, BX, BY);
            float iou = inter / (w * h + gar - inter + 1e-8f);
            if (ph) af = iou; else bf = iou;
        }
        float md = fabsf(bf + 0.5f * af - fabsf(af - bf));
        g_md[img][a][j] = md;
        atomicMax(&g_rowkey[img][a], spack(md, (unsigned)j));
        if (md > 0.0f) atomicMax(&scol[gj], spack(md, (unsigned)a));
    }
    __syncthreads();
    if (t < NB * NM) {
        if (scol[t] > 0) atomicMax(&g_colkeyF[t >> 5][t & 31], scol[t]);
    }
}

// ---------------- 3: colmax (decode rows, apply force in-shared, pos-gated column max) ---
__global__ void k_colmax() {
    int img = blockIdx.x >> 4;
    int a = (blockIdx.x & 15) * 1024 + threadIdx.x;
    __shared__ int sforce[NM];
    __shared__ ll scolp[NM];
    if (threadIdx.x < NM) {
        float v; unsigned ix;
        sdec(g_colkeyF[img][threadIdx.x], v, ix);
        sforce[threadIdx.x] = (v < 0.5f) ? (int)ix : -1;
        scolp[threadIdx.x] = NEGK;
    }
    __syncthreads();
    float v; unsigned jx;
    sdec(g_rowkey[img][a], v, jx);
    bool pos = (v >= 0.5f);
#pragma unroll
    for (int j = 0; j < NM; j++) pos |= (sforce[j] == a);
    if (pos) {
        const float4* mrow = (const float4*)g_md[img][a];
#pragma unroll
        for (int c = 0; c < 8; c++) {
            float4 m = mrow[c];
            atomicMax(&scolp[c * 4 + 0], spack(m.x, (unsigned)a));
            atomicMax(&scolp[c * 4 + 1], spack(m.y, (unsigned)a));
            atomicMax(&scolp[c * 4 + 2], spack(m.z, (unsigned)a));
            atomicMax(&scolp[c * 4 + 3], spack(m.w, (unsigned)a));
        }
    }
    __syncthreads();
    if (threadIdx.x < NM && scolp[threadIdx.x] != NEGK)
        atomicMax(&g_colkeyP[img][threadIdx.x], scolp[threadIdx.x]);
}

// ---------------- 4: loss (thread per anchor) ----------------
__global__ void k_loss(const float* __restrict__ cls, const float* __restrict__ reg,
                       const float* __restrict__ anc, const float* __restrict__ ann) {
    int img = blockIdx.x >> 5;
    int a = (blockIdx.x & 31) * 512 + threadIdx.x;
    __shared__ float smaxpos[NM];
    __shared__ int sargpos[NM];
    __shared__ int sforce[NM];
    if (threadIdx.x < NM) {
        float v; unsigned ix;
        sdec(g_colkeyP[img][threadIdx.x], v, ix);
        smaxpos[threadIdx.x] = v; sargpos[threadIdx.x] = (int)ix;
        sdec(g_colkeyF[img][threadIdx.x], v, ix);
        sforce[threadIdx.x] = (v < 0.5f) ? (int)ix : -1;
    }
    __syncthreads();

    ll rk = g_rowkey[img][a];
    g_rowkey[img][a] = 0;  // restore identity for next run
    float iomax; unsigned jm;
    sdec(rk, iomax, jm);
    bool posa = (iomax >= 0.5f);
#pragma unroll
    for (int j = 0; j < NM; j++) posa |= (sforce[j] == a);

    float csum = 0.0f, rsum = 0.0f;
    int np = 0;
    const float* crow = cls + ((size_t)img * NA + a) * NC;
    if (posa) {
        np = 1;
        float mw = -1e30f;
        const float4* mrow = (const float4*)g_md[img][a];
#pragma unroll
        for (int c = 0; c < 8; c++) {
            float4 m = mrow[c];
            float mv[4] = {m.x, m.y, m.z, m.w};
#pragma unroll
            for (int k = 0; k < 4; k++) {
                int j = c * 4 + k;
                float md = mv[k];
                bool pm = (md >= 0.5f) || (sargpos[j] == a);
                float comp = pm ? (1.0f - smaxpos[j]) : md;
                mw = fmaxf(mw, comp + md);
            }
        }
        const float* gt = ann + (size_t)(img * NM + jm) * 6;
        int lab = (int)gt[5];
#pragma unroll
        for (int c = 0; c < NC; c++) {
            float x = fminf(fmaxf(crow[c], 0.0001f), 1.0f - 0.0001f);
            if (c == lab) {
                float fw = 0.25f * (1.0f - x) * (1.0f - x);
                csum += fw * (-logf(x + 1e-6f)) * (mw + 1.0f);
            } else {
                float fw = 0.75f * x * x;
                csum += fw * (-logf(1.0f - x + 1e-6f));
            }
        }
        const float* ap = anc + (size_t)(img * NA + a) * 5;
        const float* rg = reg + (size_t)(img * NA + a) * 5;
        float tv[5];
        tv[0] = (gt[0] - ap[0]) / ap[2];
        tv[1] = (gt[1] - ap[1]) / ap[3];
        tv[2] = logf(fmaxf(gt[2], 1.0f) / ap[2]);
        tv[3] = logf(fmaxf(gt[3], 1.0f) / ap[3]);
        tv[4] = tanf(gt[4] * (PI_F / 180.0f)) - tanf(ap[4] * (PI_F / 180.0f));
        const float BETA = (float)(1.0 / 9.0);
#pragma unroll
        for (int k = 0; k < 5; k++) {
            float diff = fabsf(rg[k] - tv[k]);
            float sl = (diff < BETA) ? (0.5f * diff * diff / BETA) : (diff - 0.5f * BETA);
            rsum += sl * mw;
        }
    } else if (iomax < 0.4f) {
#pragma unroll
        for (int c = 0; c < NC; c++) {
            float x = fminf(fmaxf(crow[c], 0.0001f), 1.0f - 0.0001f);
            csum += 0.75f * x * x * (-logf(1.0f - x + 1e-6f));
        }
    }

    float wc = warp_sum_f(csum);
    float wr = warp_sum_f(rsum);
    int wn = __reduce_add_sync(0xffffffffu, np);
    __shared__ float rc[16], rr[16];
    __shared__ int rn[16];
    int warp = threadIdx.x >> 5;
    if ((threadIdx.x & 31) == 0) { rc[warp] = wc; rr[warp] = wr; rn[warp] = wn; }
    __syncthreads();
    if (threadIdx.x == 0) {
        double tc = 0.0, tr = 0.0; int tn = 0;
#pragma unroll
        for (int i = 0; i < 16; i++) { tc += (double)rc[i]; tr += (double)rr[i]; tn += rn[i]; }
        atomicAdd(&g_cls_sum[img], tc);
        atomicAdd(&g_reg_sum[img], tr);
        atomicAdd(&g_numpos[img], tn);
    }
}

// ---------------- 5: finalize + restore state ----------------
__global__ void k_final(float* __restrict__ out) {
    int t = threadIdx.x;
    if (t < NB * NM) {
        g_colkeyF[t >> 5][t & 31] = 0;
        g_colkeyP[t >> 5][t & 31] = NEGK;
    }
    if (t == 64) g_pairCount = 0;
    if (t == 0) {
        double lc = 0.0, lr = 0.0;
#pragma unroll
        for (int img = 0; img < NB; img++) {
            int np = g_numpos[img];
            lc += g_cls_sum[img] / fmax((double)np, 1.0);
            if (np > 0) lr += g_reg_sum[img] / (double)(np * 5);
            g_cls_sum[img] = 0.0; g_reg_sum[img] = 0.0; g_numpos[img] = 0;
        }
        out[0] = (float)(lc / (double)NB);
        out[1] = (float)(lr / (double)NB);
    }
}

// ---------------- launcher ----------------
extern "C" void kernel_launch(void* const* d_in, const int* in_sizes, int n_in,
                              void* d_out, int out_size) {
    const float* cls  = (const float*)d_in[0];
    const float* reg  = (const float*)d_in[1];
    const float* anc  = (const float*)d_in[2];
    const float* ranc = (const float*)d_in[3];
    const float* ann  = (const float*)d_in[4];
    float* out = (float*)d_out;

    k_filter<<<(NB * NA) / 256, 256>>>(anc, ranc, ann);
    k_heavy<<<128, 256>>>(anc, ranc, ann);
    k_colmax<<<32, 1024>>>();
    k_loss<<<64, 512>>>(cls, reg, anc, ann);
    k_final<<<1, 128>>>(out);
}

// round 4
// speedup vs baseline: 8.3873x; 1.2950x over previous
#include <cuda_runtime.h>
#include <math.h>
#include <stdint.h>

#define NB 2
#define NA 16384
#define NM 32
#define NC 15
#define PI_F 3.14159265358979323846f

typedef long long ll;

#define NEGK (-9223372036854775807ll - 1ll)
#define N4 NEGK, NEGK, NEGK, NEGK
#define N32 N4, N4, N4, N4, N4, N4, N4, N4

// ---------------- scratch (zero-init; every kernel restores state after use) ----------
__device__ float  g_md[NB][NA][NM];
__device__ ll     g_rowkey[NB][NA];                    // identity 0; reset in k_loss
__device__ ll     g_colkeyF[NB][NM];                   // identity 0; reset by last block
__device__ ll     g_colkeyP[NB][NM] = {{N32}, {N32}};  // identity NEGK; reset by last block
__device__ int    g_pairs[NB * NA * NM];
__device__ int    g_pairCount;                         // reset by last block
__device__ double g_cls_sum[NB];                       // reset by last block
__device__ double g_reg_sum[NB];
__device__ int    g_numpos[NB];
__device__ unsigned g_ticket;                          // reset by last block

// key = (float_bits(v) << 32) - idx  (v >= 0): max favors larger v, then smaller idx.
__device__ __forceinline__ ll spack(float v, unsigned idx) {
    return (ll)((unsigned long long)__float_as_uint(v) << 32) - (ll)idx;
}
__device__ __forceinline__ void sdec(ll k, float& v, unsigned& idx) {
    unsigned lo = (unsigned)(k & 0xFFFFFFFFll);
    idx = (unsigned)(-(int)lo);
    unsigned vb = (unsigned)(((unsigned long long)(k + (ll)idx)) >> 32);
    v = __uint_as_float(vb);
}

__device__ __forceinline__ float warp_sum_f(float v) {
#pragma unroll
    for (int off = 16; off > 0; off >>= 1) v += __shfl_xor_sync(0xffffffffu, v, off);
    return v;
}

// Sutherland-Hodgman on centered f32 coordinates.
__device__ float quad_inter_area_f(const float* ax, const float* ay,
                                   const float* bx, const float* by) {
    float px[10], py[10], qx[10], qy[10];
    int n = 4;
#pragma unroll
    for (int i = 0; i < 4; i++) { px[i] = ax[i]; py[i] = ay[i]; }
    for (int e = 0; e < 4; e++) {
        float x0 = bx[e], y0 = by[e];
        int e2 = (e + 1) & 3;
        float dx = bx[e2] - x0, dy = by[e2] - y0;
        int m = 0;
        float xprev = px[n - 1], yprev = py[n - 1];
        float dprev = dx * (yprev - y0) - dy * (xprev - x0);
        for (int i = 0; i < n; i++) {
            float xc = px[i], yc = py[i];
            float dc = dx * (yc - y0) - dy * (xc - x0);
            bool inc = (dc >= 0.0f), inp = (dprev >= 0.0f);
            if (inc != inp) {
                float t = dprev / (dprev - dc);
                if (m < 10) { qx[m] = xprev + t * (xc - xprev); qy[m] = yprev + t * (yc - yprev); m++; }
            }
            if (inc) { if (m < 10) { qx[m] = xc; qy[m] = yc; m++; } }
            dprev = dc; xprev = xc; yprev = yc;
        }
        n = m;
        if (n == 0) return 0.0f;
        for (int i = 0; i < n; i++) { px[i] = qx[i]; py[i] = qy[i]; }
    }
    if (n < 3) return 0.0f;
    float s = 0.0f;
    float xp = px[n - 1], yp = py[n - 1];
    for (int i = 0; i < n; i++) { s += xp * py[i] - px[i] * yp; xp = px[i]; yp = py[i]; }
    return 0.5f * fabsf(s);
}

// ---------------- 1: filter ----------------
__global__ void k_filter(const float* __restrict__ anc, const float* __restrict__ ranc,
                         const float* __restrict__ ann) {
    int idx = blockIdx.x * 128 + threadIdx.x;  // [0, NB*NA)
    int lane = threadIdx.x & 31;
    int a = idx & (NA - 1);
    int img = idx >> 14;

    __shared__ float sx1[NM], sy1[NM], sx2[NM], sy2[NM], sar[NM];
    if (threadIdx.x < NM) {
        const float* g = ann + (size_t)(img * NM + threadIdx.x) * 6;
        float cx = g[0], cy = g[1], w = g[2], h = g[3];
        float s = fmaxf(w, h) * 0.5f;
        sx1[threadIdx.x] = cx - s; sy1[threadIdx.x] = cy - s;
        sx2[threadIdx.x] = cx + s; sy2[threadIdx.x] = cy + s;
        sar[threadIdx.x] = (2.0f * s) * (2.0f * s);
    }
    __syncthreads();

    const float* p = anc + (size_t)(img * NA + a) * 5;
    const float* q = ranc + (size_t)(img * NA + a) * 5;
    float s0 = fmaxf(p[2], p[3]) * 0.5f;
    float ax1 = p[0] - s0, ay1 = p[1] - s0, ax2 = p[0] + s0, ay2 = p[1] + s0;
    float aar = (ax2 - ax1) * (ay2 - ay1);
    float s1 = fmaxf(q[2], q[3]) * 0.5f;
    float rx1 = q[0] - s1, ry1 = q[1] - s1, rx2 = q[0] + s1, ry2 = q[1] + s1;
    float rar = (rx2 - rx1) * (ry2 - ry1);

    int m = 0;
    int codes[NM];
#pragma unroll 4
    for (int j = 0; j < NM; j++) {
        float gx1 = sx1[j], gy1 = sy1[j], gx2 = sx2[j], gy2 = sy2[j], gar = sar[j];
        float wx = fmaxf(fminf(ax2, gx2) - fmaxf(ax1, gx1), 0.0f);
        float wy = fmaxf(fminf(ay2, gy2) - fmaxf(ay1, gy1), 0.0f);
        float i0 = wx * wy;
        bool f0 = (i0 / (aar + gar - i0 + 1e-8f)) >= 0.1f;
        wx = fmaxf(fminf(rx2, gx2) - fmaxf(rx1, gx1), 0.0f);
        wy = fmaxf(fminf(ry2, gy2) - fmaxf(ry1, gy1), 0.0f);
        float i1 = wx * wy;
        bool f1 = (i1 / (rar + gar - i1 + 1e-8f)) >= 0.1f;
        if (f0 | f1)
            codes[m++] = (img << 21) | (a << 7) | (j << 2) | ((int)f1 << 1) | (int)f0;
    }
    int incl = m;
#pragma unroll
    for (int off = 1; off < 32; off <<= 1) {
        int n = __shfl_up_sync(0xffffffffu, incl, off);
        if (lane >= off) incl += n;
    }
    int total = __shfl_sync(0xffffffffu, incl, 31);
    int base = 0;
    if (lane == 0 && total > 0) base = atomicAdd(&g_pairCount, total);
    base = __shfl_sync(0xffffffffu, base, 0);
    int off0 = base + incl - m;
    for (int i = 0; i < m; i++) g_pairs[off0 + i] = codes[i];
}

// ---------------- 2: heavy ----------------
__global__ void k_heavy(const float* __restrict__ anc, const float* __restrict__ ranc,
                        const float* __restrict__ ann) {
    __shared__ float sgx[NB * NM][4], sgy[NB * NM][4];
    __shared__ float sgar[NB * NM];
    __shared__ ll scol[NB * NM];
    int t = threadIdx.x;
    if (t < NB * NM) {
        int img = t >> 5, j = t & 31;
        const float* g = ann + (size_t)(img * NM + j) * 6;
        float cx = g[0], cy = g[1], w = g[2], h = g[3];
        float th = g[4] * (PI_F / 180.0f);
        float sn, cs;
        sincosf(th, &sn, &cs);
        const float lx[4] = {-0.5f, 0.5f, 0.5f, -0.5f};
        const float ly[4] = {-0.5f, -0.5f, 0.5f, 0.5f};
#pragma unroll
        for (int k = 0; k < 4; k++) {
            float dx = w * lx[k], dy = h * ly[k];
            sgx[t][k] = cx + dx * cs - dy * sn;
            sgy[t][k] = cy + dx * sn + dy * cs;
        }
        sgar[t] = w * h;
        scol[t] = 0;
    }
    __syncthreads();

    int total = g_pairCount;
    const float lx[4] = {-0.5f, 0.5f, 0.5f, -0.5f};
    const float ly[4] = {-0.5f, -0.5f, 0.5f, 0.5f};
    for (int idx = blockIdx.x * blockDim.x + threadIdx.x; idx < total;
         idx += gridDim.x * blockDim.x) {
        int code = g_pairs[idx];
        int f0 = code & 1, f1 = (code >> 1) & 1;
        int j = (code >> 2) & 31;
        int a = (code >> 7) & (NA - 1);
        int img = (code >> 21) & 1;
        int gj = img * 32 + j;
        float gar = sgar[gj];
        float bf = 0.0f, af = 0.0f;
#pragma unroll
        for (int ph = 0; ph < 2; ph++) {
            if (!(ph ? f1 : f0)) continue;
            const float* p = (ph ? ranc : anc) + (size_t)(img * NA + a) * 5;
            float cx = p[0], cy = p[1], w = p[2], h = p[3];
            float th = p[4] * (PI_F / 180.0f);
            float sn, cs;
            sincosf(th, &sn, &cs);
            float AX[4], AY[4], BX[4], BY[4];
#pragma unroll
            for (int k = 0; k < 4; k++) {
                float dx = w * lx[k], dy = h * ly[k];
                AX[k] = dx * cs - dy * sn;
                AY[k] = dx * sn + dy * cs;
                BX[k] = sgx[gj][k] - cx;
                BY[k] = sgy[gj][k] - cy;
            }
            float inter = quad_inter_area_f(AX, AY, BX, BY);
            float iou = inter / (w * h + gar - inter + 1e-8f);
            if (ph) af = iou; else bf = iou;
        }
        float md = fabsf(bf + 0.5f * af - fabsf(af - bf));
        g_md[img][a][j] = md;
        atomicMax(&g_rowkey[img][a], spack(md, (unsigned)j));
        if (md > 0.0f) atomicMax(&scol[gj], spack(md, (unsigned)a));
    }
    __syncthreads();
    if (t < NB * NM) {
        if (scol[t] > 0) atomicMax(&g_colkeyF[t >> 5][t & 31], scol[t]);
    }
}

// ---------------- 3: colmax (pos-gated column max, force applied in-shared) ------------
__global__ void k_colmax() {
    int img = blockIdx.x >> 7;
    int a = (blockIdx.x & 127) * 128 + threadIdx.x;
    __shared__ int sforce[NM];
    __shared__ ll scolp[NM];
    if (threadIdx.x < NM) {
        float v; unsigned ix;
        sdec(g_colkeyF[img][threadIdx.x], v, ix);
        sforce[threadIdx.x] = (v < 0.5f) ? (int)ix : -1;
        scolp[threadIdx.x] = NEGK;
    }
    __syncthreads();
    float v; unsigned jx;
    sdec(g_rowkey[img][a], v, jx);
    bool pos = (v >= 0.5f);
#pragma unroll
    for (int j = 0; j < NM; j++) pos |= (sforce[j] == a);
    if (pos) {
        const float4* mrow = (const float4*)g_md[img][a];
#pragma unroll
        for (int c = 0; c < 8; c++) {
            float4 m = mrow[c];
            atomicMax(&scolp[c * 4 + 0], spack(m.x, (unsigned)a));
            atomicMax(&scolp[c * 4 + 1], spack(m.y, (unsigned)a));
            atomicMax(&scolp[c * 4 + 2], spack(m.z, (unsigned)a));
            atomicMax(&scolp[c * 4 + 3], spack(m.w, (unsigned)a));
        }
    }
    __syncthreads();
    if (threadIdx.x < NM && scolp[threadIdx.x] != NEGK)
        atomicMax(&g_colkeyP[img][threadIdx.x], scolp[threadIdx.x]);
}

// ---------------- 4: loss + fused finalize (last-block ticket) ----------------
__global__ void k_loss(const float* __restrict__ cls, const float* __restrict__ reg,
                       const float* __restrict__ anc, const float* __restrict__ ann,
                       float* __restrict__ out) {
    int img = blockIdx.x >> 7;
    int a = (blockIdx.x & 127) * 128 + threadIdx.x;
    __shared__ float smaxpos[NM];
    __shared__ int sargpos[NM];
    __shared__ int sforce[NM];
    if (threadIdx.x < NM) {
        float v; unsigned ix;
        sdec(g_colkeyP[img][threadIdx.x], v, ix);
        smaxpos[threadIdx.x] = v; sargpos[threadIdx.x] = (int)ix;
        sdec(g_colkeyF[img][threadIdx.x], v, ix);
        sforce[threadIdx.x] = (v < 0.5f) ? (int)ix : -1;
    }
    __syncthreads();

    ll rk = g_rowkey[img][a];
    g_rowkey[img][a] = 0;  // restore identity for next replay
    float iomax; unsigned jm;
    sdec(rk, iomax, jm);
    bool posa = (iomax >= 0.5f);
#pragma unroll
    for (int j = 0; j < NM; j++) posa |= (sforce[j] == a);

    float csum = 0.0f, rsum = 0.0f;
    int np = 0;
    const float* crow = cls + ((size_t)img * NA + a) * NC;
    if (posa) {
        np = 1;
        float mw = -1e30f;
        const float4* mrow = (const float4*)g_md[img][a];
#pragma unroll
        for (int c = 0; c < 8; c++) {
            float4 m = mrow[c];
            float mv[4] = {m.x, m.y, m.z, m.w};
#pragma unroll
            for (int k = 0; k < 4; k++) {
                int j = c * 4 + k;
                float md = mv[k];
                bool pm = (md >= 0.5f) || (sargpos[j] == a);
                float comp = pm ? (1.0f - smaxpos[j]) : md;
                mw = fmaxf(mw, comp + md);
            }
        }
        const float* gt = ann + (size_t)(img * NM + jm) * 6;
        int lab = (int)gt[5];
#pragma unroll
        for (int c = 0; c < NC; c++) {
            float x = fminf(fmaxf(crow[c], 0.0001f), 1.0f - 0.0001f);
            if (c == lab) {
                float fw = 0.25f * (1.0f - x) * (1.0f - x);
                csum += fw * (-__logf(x + 1e-6f)) * (mw + 1.0f);
            } else {
                float fw = 0.75f * x * x;
                csum += fw * (-__logf(1.0f - x + 1e-6f));
            }
        }
        const float* ap = anc + (size_t)(img * NA + a) * 5;
        const float* rg = reg + (size_t)(img * NA + a) * 5;
        float tv[5];
        tv[0] = (gt[0] - ap[0]) / ap[2];
        tv[1] = (gt[1] - ap[1]) / ap[3];
        tv[2] = __logf(fmaxf(gt[2], 1.0f) / ap[2]);
        tv[3] = __logf(fmaxf(gt[3], 1.0f) / ap[3]);
        tv[4] = __tanf(gt[4] * (PI_F / 180.0f)) - __tanf(ap[4] * (PI_F / 180.0f));
        const float BETA = (float)(1.0 / 9.0);
#pragma unroll
        for (int k = 0; k < 5; k++) {
            float diff = fabsf(rg[k] - tv[k]);
            float sl = (diff < BETA) ? (0.5f * diff * diff / BETA) : (diff - 0.5f * BETA);
            rsum += sl * mw;
        }
    } else if (iomax < 0.4f) {
#pragma unroll
        for (int c = 0; c < NC; c++) {
            float x = fminf(fmaxf(crow[c], 0.0001f), 1.0f - 0.0001f);
            csum += 0.75f * x * x * (-__logf(1.0f - x + 1e-6f));
        }
    }

    float wc = warp_sum_f(csum);
    float wr = warp_sum_f(rsum);
    int wn = __reduce_add_sync(0xffffffffu, np);
    __shared__ float rc[4], rr[4];
    __shared__ int rn[4];
    int warp = threadIdx.x >> 5;
    if ((threadIdx.x & 31) == 0) { rc[warp] = wc; rr[warp] = wr; rn[warp] = wn; }
    __syncthreads();
    __shared__ bool last;
    if (threadIdx.x == 0) {
        double tc = 0.0, tr = 0.0; int tn = 0;
#pragma unroll
        for (int i = 0; i < 4; i++) { tc += (double)rc[i]; tr += (double)rr[i]; tn += rn[i]; }
        atomicAdd(&g_cls_sum[img], tc);
        atomicAdd(&g_reg_sum[img], tr);
        atomicAdd(&g_numpos[img], tn);
        __threadfence();
        unsigned t = atomicAdd(&g_ticket, 1u);
        last = (t == (unsigned)(gridDim.x - 1));
    }
    __syncthreads();
    if (last) {
        // finalize + restore all global state for the next graph replay
        int t = threadIdx.x;
        if (t < NB * NM) {
            g_colkeyF[t >> 5][t & 31] = 0;
            g_colkeyP[t >> 5][t & 31] = NEGK;
        }
        if (t == 64) g_pairCount = 0;
        if (t == 65) g_ticket = 0;
        if (t == 0) {
            double lc = 0.0, lr = 0.0;
#pragma unroll
            for (int i = 0; i < NB; i++) {
                int npv = g_numpos[i];
                lc += g_cls_sum[i] / fmax((double)npv, 1.0);
                if (npv > 0) lr += g_reg_sum[i] / (double)(npv * 5);
                g_cls_sum[i] = 0.0; g_reg_sum[i] = 0.0; g_numpos[i] = 0;
            }
            out[0] = (float)(lc / (double)NB);
            out[1] = (float)(lr / (double)NB);
        }
    }
}

// ---------------- launcher ----------------
extern "C" void kernel_launch(void* const* d_in, const int* in_sizes, int n_in,
                              void* d_out, int out_size) {
    const float* cls  = (const float*)d_in[0];
    const float* reg  = (const float*)d_in[1];
    const float* anc  = (const float*)d_in[2];
    const float* ranc = (const float*)d_in[3];
    const float* ann  = (const float*)d_in[4];
    float* out = (float*)d_out;

    k_filter<<<(NB * NA) / 128, 128>>>(anc, ranc, ann);
    k_heavy<<<148, 256>>>(anc, ranc, ann);
    k_colmax<<<256, 128>>>();
    k_loss<<<256, 128>>>(cls, reg, anc, ann, out);
}